// round 7
// baseline (speedup 1.0000x reference)
#include <cuda_runtime.h>
#include <cuda_fp16.h>
#include <cstdint>

#define NB 4
#define ND 128
#define NK 256
#define NS 256
#define NJ 257
#define NO 256
#define TOUT 32768

// ---------------- scratch ----------------
__device__ __half g_Af[(size_t)NB*NJ*128*ND];   // presummed OLA frames, fp16 [b][j][p][d]
__device__ __half g_W1f[NO*ND];                 // [o][d]
__device__ __half g_W2f[NO*ND];                 // [o2][e]

// smem map
#define SM_B1 0
#define SM_B2 1024
#define SM_W  2048                    // 64KB: W1 then W2
#define SM_AZ (2048 + 65536)          // 64KB: A (32K) then Z (c0|c1, 32K each)
#define SM_TOT (SM_AZ + 65536)        // 133120 B

__device__ __forceinline__ uint32_t smem_u32(const void* p) {
    uint32_t a;
    asm("{ .reg .u64 t; cvta.to.shared.u64 t, %1; cvt.u32.u64 %0, t; }" : "=r"(a) : "l"(p));
    return a;
}
__device__ __forceinline__ uint32_t swz(uint32_t row, uint32_t byteCol) {
    return row * 256u + ((((byteCol >> 4) ^ (row & 7)) << 4) | (byteCol & 15));
}
#define LDSM4(r0,r1,r2,r3,addr) \
    asm volatile("ldmatrix.sync.aligned.m8n8.x4.shared.b16 {%0,%1,%2,%3}, [%4];" \
        : "=r"(r0),"=r"(r1),"=r"(r2),"=r"(r3) : "r"(addr))

__device__ __forceinline__ void mma16816(float d[4], const uint32_t a[4], uint32_t b0, uint32_t b1) {
    asm volatile("mma.sync.aligned.m16n8k16.row.col.f32.f16.f16.f32 "
        "{%0,%1,%2,%3}, {%4,%5,%6,%7}, {%8,%9}, {%0,%1,%2,%3};"
        : "+f"(d[0]), "+f"(d[1]), "+f"(d[2]), "+f"(d[3])
        : "r"(a[0]), "r"(a[1]), "r"(a[2]), "r"(a[3]), "r"(b0), "r"(b1));
}

// 64x64 warp-tile GEMM over K=128, manual double-buffered fragments.
// a-operand rows at ar+mt*16 from uAop, b-operand rows at br+ng*16 from uBop.
__device__ __forceinline__ void gemm64(uint32_t uAop, uint32_t uBop,
                                       int ar, int br, uint32_t acb, uint32_t bcb,
                                       float acc[4][8][4])
{
    uint32_t af[2][4][4], bf[2][4][4];
#pragma unroll
    for (int mt = 0; mt < 4; mt++)
        LDSM4(af[0][mt][0], af[0][mt][1], af[0][mt][2], af[0][mt][3],
              uAop + swz(ar + mt * 16, acb));
#pragma unroll
    for (int ng = 0; ng < 4; ng++)
        LDSM4(bf[0][ng][0], bf[0][ng][1], bf[0][ng][2], bf[0][ng][3],
              uBop + swz(br + ng * 16, bcb));
#pragma unroll
    for (int ks = 0; ks < 8; ks++) {
        int cb = ks & 1, nb = cb ^ 1;
        if (ks < 7) {
            uint32_t kb = (uint32_t)(ks + 1) * 32;
#pragma unroll
            for (int mt = 0; mt < 4; mt++)
                LDSM4(af[nb][mt][0], af[nb][mt][1], af[nb][mt][2], af[nb][mt][3],
                      uAop + swz(ar + mt * 16, kb + acb));
#pragma unroll
            for (int ng = 0; ng < 4; ng++)
                LDSM4(bf[nb][ng][0], bf[nb][ng][1], bf[nb][ng][2], bf[nb][ng][3],
                      uBop + swz(br + ng * 16, kb + bcb));
        }
#pragma unroll
        for (int mt = 0; mt < 4; mt++)
#pragma unroll
            for (int ng = 0; ng < 4; ng++) {
                mma16816(acc[mt][2 * ng],     af[cb][mt], bf[cb][ng][0], bf[cb][ng][2]);
                mma16816(acc[mt][2 * ng + 1], af[cb][mt], bf[cb][ng][1], bf[cb][ng][3]);
            }
    }
}

// ---------------- prep: W fp16 convert + OLA-presummed A (proven) ----------------
__global__ void prep_all(const float* __restrict__ x, const float* __restrict__ pw_ptr,
                         const float* __restrict__ w1, const float* __restrict__ w2)
{
    int tx = threadIdx.x, ty = threadIdx.y;
    int tid = ty * 32 + tx;
    if (blockIdx.z == NB * 128) {
        int flat = (blockIdx.x * 4 + blockIdx.y) * 256 + tid;
        for (; flat < 2 * NO * ND; flat += 36 * 256) {
            if (flat < NO * ND) g_W1f[flat] = __float2half_rn(w1[flat]);
            else                g_W2f[flat - NO * ND] = __float2half_rn(w2[flat - NO * ND]);
        }
        return;
    }
    __shared__ float t[32][33];
    int b = blockIdx.z >> 7, p = blockIdx.z & 127;
    int j0 = blockIdx.x * 32, d0 = blockIdx.y * 32;
    float pw = *pw_ptr;
#pragma unroll
    for (int i = 0; i < 4; i++) {
        int d = d0 + ty + i * 8;
        int jj = j0 + tx;
        float acc = 0.f;
        if (jj < 256) {
            float v = x[(((size_t)b * ND + d) * NK + p) * NS + jj];
            acc += (v >= 0.f) ? v : pw * v;
        }
        if (jj >= 1 && jj <= 256) {
            float v = x[(((size_t)b * ND + d) * NK + p + 128) * NS + jj - 1];
            acc += (v >= 0.f) ? v : pw * v;
        }
        t[ty + i * 8][tx] = acc;
    }
    __syncthreads();
#pragma unroll
    for (int i = 0; i < 4; i++) {
        int jl = ty + i * 8;
        int jj = j0 + jl;
        if (jj <= 256) {
            g_Af[(((size_t)b * NJ + jj) * 128 + p) * ND + d0 + tx] = __float2half_rn(t[tx][jl]);
        }
    }
}

// ---------------- fused main kernel: 256 threads, 8 warps, 64x64 tiles ----------------
__global__ __launch_bounds__(256, 1) void main_kernel(
    const float* __restrict__ b1g, const float* __restrict__ b2g, float* __restrict__ out)
{
    extern __shared__ char smc[];
    uint32_t sb = smem_u32(smc);
    float* s_b1 = (float*)(smc + SM_B1);
    float* s_b2 = (float*)(smc + SM_B2);
    int tid = threadIdx.x, w = tid >> 5, lane = tid & 31;
    int j = blockIdx.x, b = blockIdx.y;

    s_b1[tid] = b1g[tid];
    s_b2[tid] = b2g[tid];

    // ---- W1 -> SM_W, A -> SM_AZ ----
    {
        const uint4* w4 = (const uint4*)g_W1f;
        for (int idx = tid; idx < 4096; idx += 256)
            *(uint4*)(smc + SM_W + swz(idx >> 4, (idx & 15) << 4)) = w4[idx];
        const uint4* a4 = (const uint4*)(g_Af + ((size_t)b * NJ + j) * (128 * ND));
        for (int idx = tid; idx < 2048; idx += 256)
            *(uint4*)(smc + SM_AZ + swz(idx >> 4, (idx & 15) << 4)) = a4[idx];
    }
    __syncthreads();

    // operand lane patterns
    int arow = lane & 15;
    uint32_t acb = (uint32_t)(lane >> 4) << 4;
    int brow = ((lane >> 3) & 1) * 8 + (lane & 7);
    uint32_t bcb = (uint32_t)((lane >> 4) & 1) << 4;
    uint32_t uW = sb + SM_W, uA = sb + SM_AZ;
    int lr = lane >> 2, lc = (lane & 3) << 1;

    float acc[4][8][4];

    // ---- GEMM1: D1[p=128][o=256] = A[p][d] * W1[o][d]; warp grid 2(p) x 4(o) ----
    int pw = (w & 1) * 64, ow = (w >> 1) * 64;
#pragma unroll
    for (int mt = 0; mt < 4; mt++)
#pragma unroll
        for (int nt = 0; nt < 8; nt++)
#pragma unroll
            for (int q = 0; q < 4; q++) acc[mt][nt][q] = 0.f;
    gemm64(uA, uW, pw + arow, ow + brow, acb, bcb, acc);
    __syncthreads();   // W1/A reads complete

    // ---- epilogue1: Z = relu(D1 + nf*b1) -> fp16, channel blocks in SM_AZ ----
    float nf = (j == 0 || j == 256) ? 1.f : 2.f;
    int cW = ow >> 7;
    char* zB = smc + SM_AZ + cW * 32768;
#pragma unroll
    for (int mt = 0; mt < 4; mt++) {
#pragma unroll
        for (int nt = 0; nt < 8; nt++) {
            int o = ow + nt * 8 + lc;
            int e = o & 127;
            float b0v = nf * s_b1[o], b1v = nf * s_b1[o + 1];
#pragma unroll
            for (int hf = 0; hf < 2; hf++) {
                int p = pw + mt * 16 + lr + hf * 8;
                __half2 hv;
                hv.x = __float2half_rn(fmaxf(acc[mt][nt][hf * 2]     + b0v, 0.f));
                hv.y = __float2half_rn(fmaxf(acc[mt][nt][hf * 2 + 1] + b1v, 0.f));
                *(uint32_t*)(zB + swz((uint32_t)p, (uint32_t)e << 1)) = *(uint32_t*)&hv;
            }
        }
    }
    // ---- W2 -> SM_W (W1 dead) ----
    {
        const uint4* w4 = (const uint4*)g_W2f;
        for (int idx = tid; idx < 4096; idx += 256)
            *(uint4*)(smc + SM_W + swz(idx >> 4, (idx & 15) << 4)) = w4[idx];
    }
    __syncthreads();

    // ---- GEMM2 (transposed): D2^T[o2=256][p=128] = W2[o2][e] * Z_c[p][e]
    //      warp grid 4(o2) x 2(p); a=W2, b=Z -> coalesced v2 stores ----
    int o2w = (w & 3) * 64, pw2 = (w >> 2) * 64;
    int l0 = j * 128 - 64;
#pragma unroll 1
    for (int c = 0; c < 2; c++) {
        uint32_t uZ = sb + SM_AZ + c * 32768;
#pragma unroll
        for (int mt = 0; mt < 4; mt++)
#pragma unroll
            for (int nt = 0; nt < 8; nt++)
#pragma unroll
                for (int q = 0; q < 4; q++) acc[mt][nt][q] = 0.f;
        gemm64(uW, uZ, o2w + arow, pw2 + brow, acb, bcb, acc);

        float* ob = out + (size_t)(b * 2 + c) * NO * TOUT;
#pragma unroll
        for (int mt = 0; mt < 4; mt++) {
#pragma unroll
            for (int hf = 0; hf < 2; hf++) {
                int o2 = o2w + mt * 16 + lr + hf * 8;
                float bo = s_b2[o2];
                float* orow = ob + (size_t)o2 * TOUT + l0;
#pragma unroll
                for (int nt = 0; nt < 8; nt++) {
                    int p = pw2 + nt * 8 + lc;
                    int l = l0 + p;
                    if (l >= 0 && l < TOUT) {
                        float2 v;
                        v.x = acc[mt][nt][hf * 2]     + bo;
                        v.y = acc[mt][nt][hf * 2 + 1] + bo;
                        *(float2*)(orow + p) = v;
                    }
                }
            }
        }
    }
}

// ---------------------------------------------------------------------------
extern "C" void kernel_launch(void* const* d_in, const int* in_sizes, int n_in,
                              void* d_out, int out_size) {
    const float* x  = (const float*)d_in[0];
    const float* pw = (const float*)d_in[1];
    const float* w1 = (const float*)d_in[2];
    const float* b1 = (const float*)d_in[3];
    const float* w2 = (const float*)d_in[4];
    const float* b2 = (const float*)d_in[5];
    float* out = (float*)d_out;

    cudaFuncSetAttribute(main_kernel, cudaFuncAttributeMaxDynamicSharedMemorySize, SM_TOT);

    prep_all<<<dim3(9, 4, NB * 128 + 1), dim3(32, 8)>>>(x, pw, w1, w2);
    main_kernel<<<dim3(NJ, NB), 256, SM_TOT>>>(b1, b2, out);
}

// round 8
// speedup vs baseline: 1.2798x; 1.2798x over previous
#include <cuda_runtime.h>
#include <cuda_fp16.h>
#include <cstdint>

#define NB 4
#define ND 128
#define NK 256
#define NS 256
#define NJ 257
#define NO 256
#define TOUT 32768

// ---------------- scratch ----------------
__device__ __half g_Af[(size_t)NB*NJ*128*ND];   // presummed OLA frames, fp16 [b][j][p][d]
__device__ __half g_W1f[NO*ND];                 // [o][d]
__device__ __half g_W2f[NO*ND];                 // [o2][e]

// smem map (bytes) — 100352 total -> 2 CTAs/SM
#define SM_B1  0
#define SM_B2  1024
#define SM_W   2048                       // 32KB: W1h0 -> W1h1 -> W2h0 -> W2h1
#define SM_ZA  (SM_W + 32768)             // 32KB: A, later Z channel 1
#define SM_ZC0 (SM_ZA + 32768)            // 32KB: Z channel 0
#define SM_TOT (SM_ZC0 + 32768)           // 100352

__device__ __forceinline__ uint32_t smem_u32(const void* p) {
    uint32_t a;
    asm("{ .reg .u64 t; cvta.to.shared.u64 t, %1; cvt.u32.u64 %0, t; }" : "=r"(a) : "l"(p));
    return a;
}
__device__ __forceinline__ uint32_t swz(uint32_t row, uint32_t byteCol) {
    return row * 256u + ((((byteCol >> 4) ^ (row & 7)) << 4) | (byteCol & 15));
}
#define LDSM4(r0,r1,r2,r3,addr) \
    asm volatile("ldmatrix.sync.aligned.m8n8.x4.shared.b16 {%0,%1,%2,%3}, [%4];" \
        : "=r"(r0),"=r"(r1),"=r"(r2),"=r"(r3) : "r"(addr))

__device__ __forceinline__ void mma16816(float d[4], const uint32_t a[4], uint32_t b0, uint32_t b1) {
    asm volatile("mma.sync.aligned.m16n8k16.row.col.f32.f16.f16.f32 "
        "{%0,%1,%2,%3}, {%4,%5,%6,%7}, {%8,%9}, {%0,%1,%2,%3};"
        : "+f"(d[0]), "+f"(d[1]), "+f"(d[2]), "+f"(d[3])
        : "r"(a[0]), "r"(a[1]), "r"(a[2]), "r"(a[3]), "r"(b0), "r"(b1));
}

// 32x64 warp-tile GEMM over K=128 (R6-proven shape): a rows ar..+16, b rows br..+48
__device__ __forceinline__ void gemm3264(uint32_t uAop, uint32_t uBop,
                                         int ar, int br, uint32_t acb, uint32_t bcb,
                                         float acc[2][8][4])
{
#pragma unroll
    for (int ks = 0; ks < 8; ks++) {
        uint32_t kb = (uint32_t)ks * 32;
        uint32_t a[2][4], bf[4][4];
#pragma unroll
        for (int mt = 0; mt < 2; mt++)
            LDSM4(a[mt][0], a[mt][1], a[mt][2], a[mt][3], uAop + swz(ar + mt * 16, kb + acb));
#pragma unroll
        for (int ng = 0; ng < 4; ng++)
            LDSM4(bf[ng][0], bf[ng][1], bf[ng][2], bf[ng][3], uBop + swz(br + ng * 16, kb + bcb));
#pragma unroll
        for (int mt = 0; mt < 2; mt++)
#pragma unroll
            for (int ng = 0; ng < 4; ng++) {
                mma16816(acc[mt][2 * ng],     a[mt], bf[ng][0], bf[ng][2]);
                mma16816(acc[mt][2 * ng + 1], a[mt], bf[ng][1], bf[ng][3]);
            }
    }
}

// ---------------- prep: W fp16 convert + OLA-presummed A (proven) ----------------
__global__ void prep_all(const float* __restrict__ x, const float* __restrict__ pw_ptr,
                         const float* __restrict__ w1, const float* __restrict__ w2)
{
    int tx = threadIdx.x, ty = threadIdx.y;
    int tid = ty * 32 + tx;
    if (blockIdx.z == NB * 128) {
        int flat = (blockIdx.x * 4 + blockIdx.y) * 256 + tid;
        for (; flat < 2 * NO * ND; flat += 36 * 256) {
            if (flat < NO * ND) g_W1f[flat] = __float2half_rn(w1[flat]);
            else                g_W2f[flat - NO * ND] = __float2half_rn(w2[flat - NO * ND]);
        }
        return;
    }
    __shared__ float t[32][33];
    int b = blockIdx.z >> 7, p = blockIdx.z & 127;
    int j0 = blockIdx.x * 32, d0 = blockIdx.y * 32;
    float pw = *pw_ptr;
#pragma unroll
    for (int i = 0; i < 4; i++) {
        int d = d0 + ty + i * 8;
        int jj = j0 + tx;
        float acc = 0.f;
        if (jj < 256) {
            float v = x[(((size_t)b * ND + d) * NK + p) * NS + jj];
            acc += (v >= 0.f) ? v : pw * v;
        }
        if (jj >= 1 && jj <= 256) {
            float v = x[(((size_t)b * ND + d) * NK + p + 128) * NS + jj - 1];
            acc += (v >= 0.f) ? v : pw * v;
        }
        t[ty + i * 8][tx] = acc;
    }
    __syncthreads();
#pragma unroll
    for (int i = 0; i < 4; i++) {
        int jl = ty + i * 8;
        int jj = j0 + jl;
        if (jj <= 256) {
            g_Af[(((size_t)b * NJ + jj) * 128 + p) * ND + d0 + tx] = __float2half_rn(t[tx][jl]);
        }
    }
}

// ---------------- fused main kernel: 256 threads, 2 CTAs/SM ----------------
__global__ __launch_bounds__(256, 2) void main_kernel(
    const float* __restrict__ b1g, const float* __restrict__ b2g, float* __restrict__ out)
{
    extern __shared__ char smc[];
    uint32_t sb = smem_u32(smc);
    float* s_b1 = (float*)(smc + SM_B1);
    float* s_b2 = (float*)(smc + SM_B2);
    int tid = threadIdx.x, w = tid >> 5, lane = tid & 31;
    int j = blockIdx.x, b = blockIdx.y;
    int pw = (w & 3) * 32, ow = (w >> 2) * 64;     // 4(p) x 2(o) grid, tile 32x64

    s_b1[tid] = b1g[tid];
    s_b2[tid] = b2g[tid];

    // operand lane patterns
    int arow = lane & 15;
    uint32_t acb = (uint32_t)(lane >> 4) << 4;
    int brow = ((lane >> 3) & 1) * 8 + (lane & 7);
    uint32_t bcb = (uint32_t)((lane >> 4) & 1) << 4;
    uint32_t uW = sb + SM_W, uZA = sb + SM_ZA, uZC0 = sb + SM_ZC0;
    int lr = lane >> 2, lc = (lane & 3) << 1;
    float nf = (j == 0 || j == 256) ? 1.f : 2.f;

    // ---- W1 half0 + A ----
    {
        const uint4* w4 = (const uint4*)g_W1f;
        for (int idx = tid; idx < 2048; idx += 256)
            *(uint4*)(smc + SM_W + swz(idx >> 4, (idx & 15) << 4)) = w4[idx];
        const uint4* a4 = (const uint4*)(g_Af + ((size_t)b * NJ + j) * (128 * ND));
        for (int idx = tid; idx < 2048; idx += 256)
            *(uint4*)(smc + SM_ZA + swz(idx >> 4, (idx & 15) << 4)) = a4[idx];
    }
    __syncthreads();

    float acc[2][8][4];

    // ---- GEMM1 halves: D1[p=128][o-half=128] = A[p][d] * W1h[o][d] ----
#pragma unroll 1
    for (int h = 0; h < 2; h++) {
        if (h == 1) {
            __syncthreads();   // G1 h0 W/A reads done (epi h0 wrote to distinct ZC0)
            const uint4* w4 = (const uint4*)g_W1f + 2048;
            for (int idx = tid; idx < 2048; idx += 256)
                *(uint4*)(smc + SM_W + swz(idx >> 4, (idx & 15) << 4)) = w4[idx];
            __syncthreads();
        }
#pragma unroll
        for (int mt = 0; mt < 2; mt++)
#pragma unroll
            for (int nt = 0; nt < 8; nt++)
#pragma unroll
                for (int q = 0; q < 4; q++) acc[mt][nt][q] = 0.f;
        gemm3264(uZA, uW, pw + arow, ow + brow, acb, bcb, acc);

        if (h == 1) __syncthreads();   // all A reads done before Zc1 overwrites A region

        // epilogue: Z_h = relu(D + nf*b1[h*128+e]) -> fp16 (h0 -> ZC0, h1 -> ZA)
        char* zB = (h == 0) ? (smc + SM_ZC0) : (smc + SM_ZA);
#pragma unroll
        for (int mt = 0; mt < 2; mt++) {
#pragma unroll
            for (int nt = 0; nt < 8; nt++) {
                int e = ow + nt * 8 + lc;
                int o = h * 128 + e;
                float b0v = nf * s_b1[o], b1v = nf * s_b1[o + 1];
#pragma unroll
                for (int hf = 0; hf < 2; hf++) {
                    int p = pw + mt * 16 + lr + hf * 8;
                    __half2 hv;
                    hv.x = __float2half_rn(fmaxf(acc[mt][nt][hf * 2]     + b0v, 0.f));
                    hv.y = __float2half_rn(fmaxf(acc[mt][nt][hf * 2 + 1] + b1v, 0.f));
                    *(uint32_t*)(zB + swz((uint32_t)p, (uint32_t)e << 1)) = *(uint32_t*)&hv;
                }
            }
        }
    }

    // ---- GEMM2 (transposed) over W2 halves: D2^T[o2h=128][p=128] = W2h[o2][e]*Z_c[p][e] ----
    int o2w = (w & 3) * 32, pw2 = (w >> 2) * 64;   // tile 32(o2) x 64(p)
    int l0 = j * 128 - 64;
#pragma unroll 1
    for (int h = 0; h < 2; h++) {
        // load W2 half (W region free: G1 reads done; for h=1, prior GEMM2 reads done)
        {
            const uint4* w4 = (const uint4*)g_W2f + h * 2048;
            for (int idx = tid; idx < 2048; idx += 256)
                *(uint4*)(smc + SM_W + swz(idx >> 4, (idx & 15) << 4)) = w4[idx];
        }
        __syncthreads();   // W2h visible + (h=0: Zc1 writes visible) (h=1: W2h0 reads done via pre-load sync below)
#pragma unroll 1
        for (int c = 0; c < 2; c++) {
            uint32_t uZ = (c == 0) ? uZC0 : uZA;
#pragma unroll
            for (int mt = 0; mt < 2; mt++)
#pragma unroll
                for (int nt = 0; nt < 8; nt++)
#pragma unroll
                    for (int q = 0; q < 4; q++) acc[mt][nt][q] = 0.f;
            gemm3264(uW, uZ, o2w + arow, pw2 + brow, acb, bcb, acc);

            float* ob = out + (size_t)(b * 2 + c) * NO * TOUT;
#pragma unroll
            for (int mt = 0; mt < 2; mt++) {
#pragma unroll
                for (int hf = 0; hf < 2; hf++) {
                    int o2 = h * 128 + o2w + mt * 16 + lr + hf * 8;
                    float bo = s_b2[o2];
                    float* orow = ob + (size_t)o2 * TOUT + l0;
#pragma unroll
                    for (int nt = 0; nt < 8; nt++) {
                        int p = pw2 + nt * 8 + lc;
                        int l = l0 + p;
                        if (l >= 0 && l < TOUT) {
                            float2 v;
                            v.x = acc[mt][nt][hf * 2]     + bo;
                            v.y = acc[mt][nt][hf * 2 + 1] + bo;
                            *(float2*)(orow + p) = v;
                        }
                    }
                }
            }
        }
        if (h == 0) __syncthreads();   // W2h0 reads done before overwrite
    }
}

// ---------------------------------------------------------------------------
extern "C" void kernel_launch(void* const* d_in, const int* in_sizes, int n_in,
                              void* d_out, int out_size) {
    const float* x  = (const float*)d_in[0];
    const float* pw = (const float*)d_in[1];
    const float* w1 = (const float*)d_in[2];
    const float* b1 = (const float*)d_in[3];
    const float* w2 = (const float*)d_in[4];
    const float* b2 = (const float*)d_in[5];
    float* out = (float*)d_out;

    cudaFuncSetAttribute(main_kernel, cudaFuncAttributeMaxDynamicSharedMemorySize, SM_TOT);

    prep_all<<<dim3(9, 4, NB * 128 + 1), dim3(32, 8)>>>(x, pw, w1, w2);
    main_kernel<<<dim3(NJ, NB), 256, SM_TOT>>>(b1, b2, out);
}

// round 9
// speedup vs baseline: 2.0313x; 1.5872x over previous
#include <cuda_runtime.h>
#include <cuda_fp16.h>
#include <cstdint>

#define NB 4
#define ND 128
#define NK 256
#define NS 256
#define NJ 257
#define NO 256
#define TOUT 32768

// ---------------- scratch ----------------
__device__ __half g_Af[(size_t)NB*NJ*128*ND];   // presummed OLA frames, fp16 [b][j][p][d]
__device__ __half g_W1f[NO*ND];                 // [o][d]
__device__ __half g_W2f[NO*ND];                 // [o2][e]

// smem map (bytes) — all regions disjoint; 231424 total (1 CTA/SM)
#define SM_B1 0
#define SM_B2 1024
#define SM_W1 2048
#define SM_W2 (SM_W1 + 65536)
#define SM_A  (SM_W2 + 65536)
#define SM_Z  (SM_A + 32768)
#define SM_TOT (SM_Z + 65536)          // 231424

__device__ __forceinline__ uint32_t smem_u32(const void* p) {
    uint32_t a;
    asm("{ .reg .u64 t; cvta.to.shared.u64 t, %1; cvt.u32.u64 %0, t; }" : "=r"(a) : "l"(p));
    return a;
}
__device__ __forceinline__ uint32_t swz(uint32_t row, uint32_t byteCol) {
    return row * 256u + ((((byteCol >> 4) ^ (row & 7)) << 4) | (byteCol & 15));
}
#define LDSM4(r0,r1,r2,r3,addr) \
    asm volatile("ldmatrix.sync.aligned.m8n8.x4.shared.b16 {%0,%1,%2,%3}, [%4];" \
        : "=r"(r0),"=r"(r1),"=r"(r2),"=r"(r3) : "r"(addr))
#define CP16(dst, src) \
    asm volatile("cp.async.cg.shared.global [%0], [%1], 16;" :: "r"(dst), "l"(src) : "memory")
#define CP_COMMIT() asm volatile("cp.async.commit_group;" ::: "memory")
#define CP_WAIT(n)  asm volatile("cp.async.wait_group %0;" :: "n"(n) : "memory")

__device__ __forceinline__ void mma16816(float d[4], const uint32_t a[4], uint32_t b0, uint32_t b1) {
    asm volatile("mma.sync.aligned.m16n8k16.row.col.f32.f16.f16.f32 "
        "{%0,%1,%2,%3}, {%4,%5,%6,%7}, {%8,%9}, {%0,%1,%2,%3};"
        : "+f"(d[0]), "+f"(d[1]), "+f"(d[2]), "+f"(d[3])
        : "r"(a[0]), "r"(a[1]), "r"(a[2]), "r"(a[3]), "r"(b0), "r"(b1));
}

// ---------------- prep: W fp16 convert + OLA-presummed A (proven) ----------------
__global__ void prep_all(const float* __restrict__ x, const float* __restrict__ pw_ptr,
                         const float* __restrict__ w1, const float* __restrict__ w2)
{
    int tx = threadIdx.x, ty = threadIdx.y;
    int tid = ty * 32 + tx;
    if (blockIdx.z == NB * 128) {
        int flat = (blockIdx.x * 4 + blockIdx.y) * 256 + tid;
        for (; flat < 2 * NO * ND; flat += 36 * 256) {
            if (flat < NO * ND) g_W1f[flat] = __float2half_rn(w1[flat]);
            else                g_W2f[flat - NO * ND] = __float2half_rn(w2[flat - NO * ND]);
        }
        return;
    }
    __shared__ float t[32][33];
    int b = blockIdx.z >> 7, p = blockIdx.z & 127;
    int j0 = blockIdx.x * 32, d0 = blockIdx.y * 32;
    float pw = *pw_ptr;
#pragma unroll
    for (int i = 0; i < 4; i++) {
        int d = d0 + ty + i * 8;
        int jj = j0 + tx;
        float acc = 0.f;
        if (jj < 256) {
            float v = x[(((size_t)b * ND + d) * NK + p) * NS + jj];
            acc += (v >= 0.f) ? v : pw * v;
        }
        if (jj >= 1 && jj <= 256) {
            float v = x[(((size_t)b * ND + d) * NK + p + 128) * NS + jj - 1];
            acc += (v >= 0.f) ? v : pw * v;
        }
        t[ty + i * 8][tx] = acc;
    }
    __syncthreads();
#pragma unroll
    for (int i = 0; i < 4; i++) {
        int jl = ty + i * 8;
        int jj = j0 + jl;
        if (jj <= 256) {
            g_Af[(((size_t)b * NJ + jj) * 128 + p) * ND + d0 + tx] = __float2half_rn(t[tx][jl]);
        }
    }
}

// ---------------- fused main kernel: 512 threads, async prologue ----------------
__global__ __launch_bounds__(512, 1) void main_kernel(
    const float* __restrict__ b1g, const float* __restrict__ b2g, float* __restrict__ out)
{
    extern __shared__ char smc[];
    uint32_t sb = smem_u32(smc);
    float* s_b1 = (float*)(smc + SM_B1);
    float* s_b2 = (float*)(smc + SM_B2);
    int tid = threadIdx.x, w = tid >> 5, lane = tid & 31;
    int j = blockIdx.x, b = blockIdx.y;
    int pw = (w & 3) * 32, ow = (w >> 2) * 64;     // GEMM1: 4(p) x 4(o), tile 32x64

    if (tid < 256) { s_b1[tid] = b1g[tid]; s_b2[tid] = b2g[tid]; }

    // ---- async prologue: group0 = W1 + A (needed for GEMM1), group1 = W2 ----
    {
        const uint4* w14 = (const uint4*)g_W1f;
#pragma unroll
        for (int q = 0; q < 8; q++) {
            int idx = tid + q * 512;
            CP16(sb + SM_W1 + swz(idx >> 4, (idx & 15) << 4), (const void*)(w14 + idx));
        }
        const uint4* a4 = (const uint4*)(g_Af + ((size_t)b * NJ + j) * (128 * ND));
#pragma unroll
        for (int q = 0; q < 4; q++) {
            int idx = tid + q * 512;
            CP16(sb + SM_A + swz(idx >> 4, (idx & 15) << 4), (const void*)(a4 + idx));
        }
        CP_COMMIT();
        const uint4* w24 = (const uint4*)g_W2f;
#pragma unroll
        for (int q = 0; q < 8; q++) {
            int idx = tid + q * 512;
            CP16(sb + SM_W2 + swz(idx >> 4, (idx & 15) << 4), (const void*)(w24 + idx));
        }
        CP_COMMIT();
    }
    CP_WAIT(1);          // W1 + A landed (W2 still in flight, overlaps GEMM1)
    __syncthreads();

    // operand lane patterns
    int arow = lane & 15;
    uint32_t acb = (uint32_t)(lane >> 4) << 4;
    int brow = ((lane >> 3) & 1) * 8 + (lane & 7);
    uint32_t bcb = (uint32_t)((lane >> 4) & 1) << 4;
    uint32_t uW1 = sb + SM_W1, uW2 = sb + SM_W2, uA = sb + SM_A;
    int lr = lane >> 2, lc = (lane & 3) << 1;

    float acc[2][8][4];

    // ---- GEMM1: D1[p=128][o=256] = A[p][d] * W1[o][d] ----
#pragma unroll
    for (int mt = 0; mt < 2; mt++)
#pragma unroll
        for (int nt = 0; nt < 8; nt++)
#pragma unroll
            for (int q = 0; q < 4; q++) acc[mt][nt][q] = 0.f;
    {
        int ar = pw + arow, br = ow + brow;
#pragma unroll
        for (int ks = 0; ks < 8; ks++) {
            uint32_t kb = (uint32_t)ks * 32;
            uint32_t a[2][4], bf[4][4];
#pragma unroll
            for (int mt = 0; mt < 2; mt++)
                LDSM4(a[mt][0], a[mt][1], a[mt][2], a[mt][3], uA + swz(ar + mt * 16, kb + acb));
#pragma unroll
            for (int ng = 0; ng < 4; ng++)
                LDSM4(bf[ng][0], bf[ng][1], bf[ng][2], bf[ng][3], uW1 + swz(br + ng * 16, kb + bcb));
#pragma unroll
            for (int mt = 0; mt < 2; mt++)
#pragma unroll
                for (int ng = 0; ng < 4; ng++) {
                    mma16816(acc[mt][2 * ng],     a[mt], bf[ng][0], bf[ng][2]);
                    mma16816(acc[mt][2 * ng + 1], a[mt], bf[ng][1], bf[ng][3]);
                }
        }
    }

    // ---- epilogue1 (NO sync needed: Z region disjoint from W1/A) ----
    float nf = (j == 0 || j == 256) ? 1.f : 2.f;
    int cW = ow >> 7;
    char* zB = smc + SM_Z + cW * 32768;
#pragma unroll
    for (int mt = 0; mt < 2; mt++) {
#pragma unroll
        for (int nt = 0; nt < 8; nt++) {
            int o = ow + nt * 8 + lc;
            int e = o & 127;
            float b0v = nf * s_b1[o], b1v = nf * s_b1[o + 1];
#pragma unroll
            for (int hf = 0; hf < 2; hf++) {
                int p = pw + mt * 16 + lr + hf * 8;
                __half2 hv;
                hv.x = __float2half_rn(fmaxf(acc[mt][nt][hf * 2]     + b0v, 0.f));
                hv.y = __float2half_rn(fmaxf(acc[mt][nt][hf * 2 + 1] + b1v, 0.f));
                *(uint32_t*)(zB + swz((uint32_t)p, (uint32_t)e << 1)) = *(uint32_t*)&hv;
            }
        }
    }
    CP_WAIT(0);          // W2 landed
    __syncthreads();     // Z visible to all + W2 visible

    // ---- GEMM2 (transposed): D2^T[o2=256][p=128] = W2[o2][e] * Z_c[p][e] ----
    int o2w = (w & 7) * 32, pw2 = (w >> 3) * 64;
    int l0 = j * 128 - 64;
    int ar2 = o2w + arow, br2 = pw2 + brow;
#pragma unroll 1
    for (int c = 0; c < 2; c++) {
        uint32_t uZ = sb + SM_Z + c * 32768;
#pragma unroll
        for (int mt = 0; mt < 2; mt++)
#pragma unroll
            for (int nt = 0; nt < 8; nt++)
#pragma unroll
                for (int q = 0; q < 4; q++) acc[mt][nt][q] = 0.f;
#pragma unroll
        for (int ks = 0; ks < 8; ks++) {
            uint32_t kb = (uint32_t)ks * 32;
            uint32_t a[2][4], bf[4][4];
#pragma unroll
            for (int mt = 0; mt < 2; mt++)
                LDSM4(a[mt][0], a[mt][1], a[mt][2], a[mt][3], uW2 + swz(ar2 + mt * 16, kb + acb));
#pragma unroll
            for (int ng = 0; ng < 4; ng++)
                LDSM4(bf[ng][0], bf[ng][1], bf[ng][2], bf[ng][3], uZ + swz(br2 + ng * 16, kb + bcb));
#pragma unroll
            for (int mt = 0; mt < 2; mt++)
#pragma unroll
                for (int ng = 0; ng < 4; ng++) {
                    mma16816(acc[mt][2 * ng],     a[mt], bf[ng][0], bf[ng][2]);
                    mma16816(acc[mt][2 * ng + 1], a[mt], bf[ng][1], bf[ng][3]);
                }
        }
        // ---- out epilogue: coalesced float2 stores ----
        float* ob = out + (size_t)(b * 2 + c) * NO * TOUT;
#pragma unroll
        for (int mt = 0; mt < 2; mt++) {
#pragma unroll
            for (int hf = 0; hf < 2; hf++) {
                int o2 = o2w + mt * 16 + lr + hf * 8;
                float bo = s_b2[o2];
                float* orow = ob + (size_t)o2 * TOUT + l0;
#pragma unroll
                for (int nt = 0; nt < 8; nt++) {
                    int p = pw2 + nt * 8 + lc;
                    int l = l0 + p;
                    if (l >= 0 && l < TOUT) {
                        float2 v;
                        v.x = acc[mt][nt][hf * 2]     + bo;
                        v.y = acc[mt][nt][hf * 2 + 1] + bo;
                        *(float2*)(orow + p) = v;
                    }
                }
            }
        }
    }
}

// ---------------------------------------------------------------------------
extern "C" void kernel_launch(void* const* d_in, const int* in_sizes, int n_in,
                              void* d_out, int out_size) {
    const float* x  = (const float*)d_in[0];
    const float* pw = (const float*)d_in[1];
    const float* w1 = (const float*)d_in[2];
    const float* b1 = (const float*)d_in[3];
    const float* w2 = (const float*)d_in[4];
    const float* b2 = (const float*)d_in[5];
    float* out = (float*)d_out;

    cudaFuncSetAttribute(main_kernel, cudaFuncAttributeMaxDynamicSharedMemorySize, SM_TOT);

    prep_all<<<dim3(9, 4, NB * 128 + 1), dim3(32, 8)>>>(x, pw, w1, w2);
    main_kernel<<<dim3(NJ, NB), 512, SM_TOT>>>(b1, b2, out);
}

// round 12
// speedup vs baseline: 2.0348x; 1.0017x over previous
#include <cuda_runtime.h>
#include <cuda_fp16.h>
#include <cstdint>

#define NB 4
#define ND 128
#define NK 256
#define NS 256
#define NJ 257
#define NO 256
#define TOUT 32768

// ---------------- scratch ----------------
__device__ __half g_Af[(size_t)NB*NJ*128*ND];   // presummed OLA frames, fp16 [b][j][p][d]
__device__ __half g_W1f[NO*ND];                 // [o][d]
__device__ __half g_W2f[NO*ND];                 // [o2][e]

// smem map (bytes) — all regions disjoint; 231424 total (1 CTA/SM)
#define SM_B1 0
#define SM_B2 1024
#define SM_W1 2048
#define SM_W2 (SM_W1 + 65536)
#define SM_A  (SM_W2 + 65536)
#define SM_Z  (SM_A + 32768)
#define SM_TOT (SM_Z + 65536)          // 231424

__device__ __forceinline__ uint32_t smem_u32(const void* p) {
    uint32_t a;
    asm("{ .reg .u64 t; cvta.to.shared.u64 t, %1; cvt.u32.u64 %0, t; }" : "=r"(a) : "l"(p));
    return a;
}
// standard swizzle (W/A regions)
__device__ __forceinline__ uint32_t swz(uint32_t row, uint32_t byteCol) {
    return row * 256u + ((((byteCol >> 4) ^ (row & 7)) << 4) | (byteCol & 15));
}
// Z-region swizzle: permuted rows put variation in bit3+, fold row>>3 into the XOR
__device__ __forceinline__ uint32_t swzZ(uint32_t row, uint32_t byteCol) {
    uint32_t f = (row ^ (row >> 3)) & 7u;
    return row * 256u + ((((byteCol >> 4) ^ f) << 4) | (byteCol & 15));
}
#define LDSM4(r0,r1,r2,r3,addr) \
    asm volatile("ldmatrix.sync.aligned.m8n8.x4.shared.b16 {%0,%1,%2,%3}, [%4];" \
        : "=r"(r0),"=r"(r1),"=r"(r2),"=r"(r3) : "r"(addr))
#define CP16(dst, src) \
    asm volatile("cp.async.cg.shared.global [%0], [%1], 16;" :: "r"(dst), "l"(src) : "memory")
#define CP_COMMIT() asm volatile("cp.async.commit_group;" ::: "memory")
#define CP_WAIT(n)  asm volatile("cp.async.wait_group %0;" :: "n"(n) : "memory")

__device__ __forceinline__ void mma16816(float d[4], const uint32_t a[4], uint32_t b0, uint32_t b1) {
    asm volatile("mma.sync.aligned.m16n8k16.row.col.f32.f16.f16.f32 "
        "{%0,%1,%2,%3}, {%4,%5,%6,%7}, {%8,%9}, {%0,%1,%2,%3};"
        : "+f"(d[0]), "+f"(d[1]), "+f"(d[2]), "+f"(d[3])
        : "r"(a[0]), "r"(a[1]), "r"(a[2]), "r"(a[3]), "r"(b0), "r"(b1));
}

// ---------------- prep: W fp16 convert + OLA-presummed A (widened writes) ----------------
// grid (9, 2, NB*128 + 1), block (32, 8)
__global__ void prep_all(const float* __restrict__ x, const float* __restrict__ pw_ptr,
                         const float* __restrict__ w1, const float* __restrict__ w2)
{
    int tx = threadIdx.x, ty = threadIdx.y;
    int tid = ty * 32 + tx;
    if (blockIdx.z == NB * 128) {
        int flat = ((int)blockIdx.x * 2 + (int)blockIdx.y) * 256 + tid;
        for (; flat < 2 * NO * ND; flat += 18 * 256) {
            if (flat < NO * ND) g_W1f[flat] = __float2half_rn(w1[flat]);
            else                g_W2f[flat - NO * ND] = __float2half_rn(w2[flat - NO * ND]);
        }
        return;
    }
    __shared__ float t[64][33];
    int b = blockIdx.z >> 7, p = blockIdx.z & 127;
    int j0 = blockIdx.x * 32, d0 = blockIdx.y * 64;
    float pw = *pw_ptr;
#pragma unroll
    for (int i = 0; i < 8; i++) {
        int d = d0 + ty + i * 8;
        int jj = j0 + tx;
        float acc = 0.f;
        if (jj < 256) {
            float v = x[(((size_t)b * ND + d) * NK + p) * NS + jj];
            acc += (v >= 0.f) ? v : pw * v;
        }
        if (jj >= 1 && jj <= 256) {
            float v = x[(((size_t)b * ND + d) * NK + p + 128) * NS + jj - 1];
            acc += (v >= 0.f) ? v : pw * v;
        }
        t[ty + i * 8][tx] = acc;
    }
    __syncthreads();
#pragma unroll
    for (int i = 0; i < 4; i++) {
        int jl = ty + i * 8;
        int jj = j0 + jl;
        if (jj <= 256) {
            __half2 hv;
            hv.x = __float2half_rn(t[2 * tx][jl]);
            hv.y = __float2half_rn(t[2 * tx + 1][jl]);
            *(__half2*)&g_Af[(((size_t)b * NJ + jj) * 128 + p) * ND + d0 + 2 * tx] = hv;
        }
    }
}

// ---------------- fused main kernel: 512 threads, async prologue, permuted Z ----------------
__global__ __launch_bounds__(512, 1) void main_kernel(
    const float* __restrict__ b1g, const float* __restrict__ b2g, float* __restrict__ out)
{
    extern __shared__ char smc[];
    uint32_t sb = smem_u32(smc);
    float* s_b1 = (float*)(smc + SM_B1);
    float* s_b2 = (float*)(smc + SM_B2);
    int tid = threadIdx.x, w = tid >> 5, lane = tid & 31;
    int j = blockIdx.x, b = blockIdx.y;
    int pw = (w & 3) * 32, ow = (w >> 2) * 64;     // GEMM1: 4(p) x 4(o), tile 32x64

    if (tid < 256) { s_b1[tid] = b1g[tid]; s_b2[tid] = b2g[tid]; }

    // ---- async prologue: group0 = W1 + A, group1 = W2 (lands during GEMM1) ----
    {
        const uint4* w14 = (const uint4*)g_W1f;
#pragma unroll
        for (int q = 0; q < 8; q++) {
            int idx = tid + q * 512;
            CP16(sb + SM_W1 + swz(idx >> 4, (idx & 15) << 4), (const void*)(w14 + idx));
        }
        const uint4* a4 = (const uint4*)(g_Af + ((size_t)b * NJ + j) * (128 * ND));
#pragma unroll
        for (int q = 0; q < 4; q++) {
            int idx = tid + q * 512;
            CP16(sb + SM_A + swz(idx >> 4, (idx & 15) << 4), (const void*)(a4 + idx));
        }
        CP_COMMIT();
        const uint4* w24 = (const uint4*)g_W2f;
#pragma unroll
        for (int q = 0; q < 8; q++) {
            int idx = tid + q * 512;
            CP16(sb + SM_W2 + swz(idx >> 4, (idx & 15) << 4), (const void*)(w24 + idx));
        }
        CP_COMMIT();
    }
    CP_WAIT(1);
    __syncthreads();

    // operand lane patterns
    int arow = lane & 15;
    uint32_t acb = (uint32_t)(lane >> 4) << 4;
    int brow = ((lane >> 3) & 1) * 8 + (lane & 7);
    uint32_t bcb = (uint32_t)((lane >> 4) & 1) << 4;
    uint32_t uW1 = sb + SM_W1, uW2 = sb + SM_W2, uA = sb + SM_A;
    int lr = lane >> 2, lc = (lane & 3) << 1;

    float acc[2][8][4];

    // ---- GEMM1: D1[p=128][o=256] = A[p][d] * W1[o][d] ----
#pragma unroll
    for (int mt = 0; mt < 2; mt++)
#pragma unroll
        for (int nt = 0; nt < 8; nt++)
#pragma unroll
            for (int q = 0; q < 4; q++) acc[mt][nt][q] = 0.f;
    {
        int ar = pw + arow, br = ow + brow;
#pragma unroll
        for (int ks = 0; ks < 8; ks++) {
            uint32_t kb = (uint32_t)ks * 32;
            uint32_t a[2][4], bf[4][4];
#pragma unroll
            for (int mt = 0; mt < 2; mt++)
                LDSM4(a[mt][0], a[mt][1], a[mt][2], a[mt][3], uA + swz(ar + mt * 16, kb + acb));
#pragma unroll
            for (int ng = 0; ng < 4; ng++)
                LDSM4(bf[ng][0], bf[ng][1], bf[ng][2], bf[ng][3], uW1 + swz(br + ng * 16, kb + bcb));
#pragma unroll
            for (int mt = 0; mt < 2; mt++)
#pragma unroll
                for (int ng = 0; ng < 4; ng++) {
                    mma16816(acc[mt][2 * ng],     a[mt], bf[ng][0], bf[ng][2]);
                    mma16816(acc[mt][2 * ng + 1], a[mt], bf[ng][1], bf[ng][3]);
                }
        }
    }

    // ---- epilogue1: Z = relu(D1 + nf*b1) -> fp16 at PERMUTED rows (no sync needed) ----
    // row = (p&64) + perm(p&63): perm maps p_local = 16q+4t+2v+b -> 16q+8v+2t+b
    float nf = (j == 0 || j == 256) ? 1.f : 2.f;
    int cW = ow >> 7;
    char* zB = smc + SM_Z + cW * 32768;
#pragma unroll
    for (int mt = 0; mt < 2; mt++) {
#pragma unroll
        for (int nt = 0; nt < 8; nt++) {
            int o = ow + nt * 8 + lc;
            int e = o & 127;
            float b0v = nf * s_b1[o], b1v = nf * s_b1[o + 1];
#pragma unroll
            for (int hf = 0; hf < 2; hf++) {
                int p = pw + mt * 16 + lr + hf * 8;
                int pl = p & 63;
                int nl = ((pl >> 4) << 4) + (((pl >> 1) & 1) << 3)
                       + (((pl >> 2) & 3) << 1) + (pl & 1);
                uint32_t row = (uint32_t)((p & 64) + nl);
                __half2 hv;
                hv.x = __float2half_rn(fmaxf(acc[mt][nt][hf * 2]     + b0v, 0.f));
                hv.y = __float2half_rn(fmaxf(acc[mt][nt][hf * 2 + 1] + b1v, 0.f));
                *(uint32_t*)(zB + swzZ(row, (uint32_t)e << 1)) = *(uint32_t*)&hv;
            }
        }
    }
    CP_WAIT(0);          // W2 landed
    __syncthreads();     // Z + W2 visible

    // ---- GEMM2 (transposed): D2^T[o2=256][p=128] = W2[o2][e] * Z_c[p][e] ----
    int o2w = (w & 7) * 32, pw2 = (w >> 3) * 64;
    int l0 = j * 128 - 64;
    int ar2 = o2w + arow, br2 = pw2 + brow;
    int t4 = lane & 3;
    bool valid = (j > 0 || pw2 == 64) && (j < 256 || pw2 == 0);
#pragma unroll 1
    for (int c = 0; c < 2; c++) {
        uint32_t uZ = sb + SM_Z + c * 32768;
#pragma unroll
        for (int mt = 0; mt < 2; mt++)
#pragma unroll
            for (int nt = 0; nt < 8; nt++)
#pragma unroll
                for (int q = 0; q < 4; q++) acc[mt][nt][q] = 0.f;
#pragma unroll
        for (int ks = 0; ks < 8; ks++) {
            uint32_t kb = (uint32_t)ks * 32;
            uint32_t a[2][4], bf[4][4];
#pragma unroll
            for (int mt = 0; mt < 2; mt++)
                LDSM4(a[mt][0], a[mt][1], a[mt][2], a[mt][3], uW2 + swz(ar2 + mt * 16, kb + acb));
#pragma unroll
            for (int ng = 0; ng < 4; ng++)
                LDSM4(bf[ng][0], bf[ng][1], bf[ng][2], bf[ng][3], uZ + swzZ(br2 + ng * 16, kb + bcb));
#pragma unroll
            for (int mt = 0; mt < 2; mt++)
#pragma unroll
                for (int ng = 0; ng < 4; ng++) {
                    mma16816(acc[mt][2 * ng],     a[mt], bf[ng][0], bf[ng][2]);
                    mma16816(acc[mt][2 * ng + 1], a[mt], bf[ng][1], bf[ng][3]);
                }
        }
        // ---- out epilogue: thanks to Z permutation, 4x float4 contiguous per row ----
        if (valid) {
            float* ob = out + (size_t)(b * 2 + c) * NO * TOUT;
#pragma unroll
            for (int mt = 0; mt < 2; mt++) {
#pragma unroll
                for (int hf = 0; hf < 2; hf++) {
                    int o2 = o2w + mt * 16 + lr + hf * 8;
                    float bo = s_b2[o2];
                    float* orow = ob + (size_t)o2 * TOUT + l0 + pw2 + t4 * 4;
#pragma unroll
                    for (int q = 0; q < 4; q++) {
                        float4 v;
                        v.x = acc[mt][2 * q][hf * 2]         + bo;
                        v.y = acc[mt][2 * q][hf * 2 + 1]     + bo;
                        v.z = acc[mt][2 * q + 1][hf * 2]     + bo;
                        v.w = acc[mt][2 * q + 1][hf * 2 + 1] + bo;
                        *(float4*)(orow + 16 * q) = v;
                    }
                }
            }
        }
    }
}

// ---------------------------------------------------------------------------
extern "C" void kernel_launch(void* const* d_in, const int* in_sizes, int n_in,
                              void* d_out, int out_size) {
    const float* x  = (const float*)d_in[0];
    const float* pw = (const float*)d_in[1];
    const float* w1 = (const float*)d_in[2];
    const float* b1 = (const float*)d_in[3];
    const float* w2 = (const float*)d_in[4];
    const float* b2 = (const float*)d_in[5];
    float* out = (float*)d_out;

    cudaFuncSetAttribute(main_kernel, cudaFuncAttributeMaxDynamicSharedMemorySize, SM_TOT);

    prep_all<<<dim3(9, 2, NB * 128 + 1), dim3(32, 8)>>>(x, pw, w1, w2);
    main_kernel<<<dim3(NJ, NB), 512, SM_TOT>>>(b1, b2, out);
}

// round 13
// speedup vs baseline: 2.0440x; 1.0046x over previous
#include <cuda_runtime.h>
#include <cuda_fp16.h>
#include <cstdint>

#define NB 4
#define ND 128
#define NK 256
#define NS 256
#define NJ 257
#define NO 256
#define TOUT 32768

// ---------------- scratch ----------------
__device__ __half g_Af[(size_t)NB*NJ*128*ND];   // presummed OLA frames, fp16 [b][j][p][d]
__device__ __half g_W1f[NO*ND];                 // [o][d]
__device__ __half g_W2f[NO*ND];                 // [o2][e]

// smem map (bytes) — all regions disjoint; 231424 total (1 CTA/SM)
#define SM_B1 0
#define SM_B2 1024
#define SM_W1 2048
#define SM_W2 (SM_W1 + 65536)
#define SM_A  (SM_W2 + 65536)
#define SM_Z  (SM_A + 32768)
#define SM_TOT (SM_Z + 65536)          // 231424

__device__ __forceinline__ uint32_t smem_u32(const void* p) {
    uint32_t a;
    asm("{ .reg .u64 t; cvta.to.shared.u64 t, %1; cvt.u32.u64 %0, t; }" : "=r"(a) : "l"(p));
    return a;
}
// standard swizzle (W/A regions)
__device__ __forceinline__ uint32_t swz(uint32_t row, uint32_t byteCol) {
    return row * 256u + ((((byteCol >> 4) ^ (row & 7)) << 4) | (byteCol & 15));
}
// Z-region swizzle (permuted rows)
__device__ __forceinline__ uint32_t swzZ(uint32_t row, uint32_t byteCol) {
    uint32_t f = (row ^ (row >> 3)) & 7u;
    return row * 256u + ((((byteCol >> 4) ^ f) << 4) | (byteCol & 15));
}
#define LDSM4(r0,r1,r2,r3,addr) \
    asm volatile("ldmatrix.sync.aligned.m8n8.x4.shared.b16 {%0,%1,%2,%3}, [%4];" \
        : "=r"(r0),"=r"(r1),"=r"(r2),"=r"(r3) : "r"(addr))
#define CP16(dst, src) \
    asm volatile("cp.async.cg.shared.global [%0], [%1], 16;" :: "r"(dst), "l"(src) : "memory")
#define CP_COMMIT() asm volatile("cp.async.commit_group;" ::: "memory")
#define CP_WAIT(n)  asm volatile("cp.async.wait_group %0;" :: "n"(n) : "memory")

__device__ __forceinline__ void mma16816(float d[4], const uint32_t a[4], uint32_t b0, uint32_t b1) {
    asm volatile("mma.sync.aligned.m16n8k16.row.col.f32.f16.f16.f32 "
        "{%0,%1,%2,%3}, {%4,%5,%6,%7}, {%8,%9}, {%0,%1,%2,%3};"
        : "+f"(d[0]), "+f"(d[1]), "+f"(d[2]), "+f"(d[3])
        : "r"(a[0]), "r"(a[1]), "r"(a[2]), "r"(a[3]), "r"(b0), "r"(b1));
}

// 32x64 warp-tile GEMM over K=128 with EXPLICIT fragment double-buffering.
// BZ: b-operand lives in the permuted-Z region (swzZ addressing).
template<bool BZ>
__device__ __forceinline__ void gemm_pipe(uint32_t uAop, uint32_t uBop,
                                          int ar, int br, uint32_t acb, uint32_t bcb,
                                          float acc[2][8][4])
{
    uint32_t af[2][2][4], bf[2][4][4];
#pragma unroll
    for (int mt = 0; mt < 2; mt++)
        LDSM4(af[0][mt][0], af[0][mt][1], af[0][mt][2], af[0][mt][3],
              uAop + swz(ar + mt * 16, acb));
#pragma unroll
    for (int ng = 0; ng < 4; ng++) {
        uint32_t off = BZ ? swzZ(br + ng * 16, bcb) : swz(br + ng * 16, bcb);
        LDSM4(bf[0][ng][0], bf[0][ng][1], bf[0][ng][2], bf[0][ng][3], uBop + off);
    }
#pragma unroll
    for (int ks = 0; ks < 8; ks++) {
        int cur = ks & 1, nxt = cur ^ 1;
        if (ks < 7) {
            uint32_t kb = (uint32_t)(ks + 1) * 32;
#pragma unroll
            for (int mt = 0; mt < 2; mt++)
                LDSM4(af[nxt][mt][0], af[nxt][mt][1], af[nxt][mt][2], af[nxt][mt][3],
                      uAop + swz(ar + mt * 16, kb + acb));
#pragma unroll
            for (int ng = 0; ng < 4; ng++) {
                uint32_t off = BZ ? swzZ(br + ng * 16, kb + bcb) : swz(br + ng * 16, kb + bcb);
                LDSM4(bf[nxt][ng][0], bf[nxt][ng][1], bf[nxt][ng][2], bf[nxt][ng][3], uBop + off);
            }
        }
#pragma unroll
        for (int mt = 0; mt < 2; mt++)
#pragma unroll
            for (int ng = 0; ng < 4; ng++) {
                mma16816(acc[mt][2 * ng],     af[cur][mt], bf[cur][ng][0], bf[cur][ng][2]);
                mma16816(acc[mt][2 * ng + 1], af[cur][mt], bf[cur][ng][1], bf[cur][ng][3]);
            }
    }
}

// ---------------- prep: W fp16 convert + OLA-presummed A (proven) ----------------
__global__ void prep_all(const float* __restrict__ x, const float* __restrict__ pw_ptr,
                         const float* __restrict__ w1, const float* __restrict__ w2)
{
    int tx = threadIdx.x, ty = threadIdx.y;
    int tid = ty * 32 + tx;
    if (blockIdx.z == NB * 128) {
        int flat = ((int)blockIdx.x * 2 + (int)blockIdx.y) * 256 + tid;
        for (; flat < 2 * NO * ND; flat += 18 * 256) {
            if (flat < NO * ND) g_W1f[flat] = __float2half_rn(w1[flat]);
            else                g_W2f[flat - NO * ND] = __float2half_rn(w2[flat - NO * ND]);
        }
        return;
    }
    __shared__ float t[64][33];
    int b = blockIdx.z >> 7, p = blockIdx.z & 127;
    int j0 = blockIdx.x * 32, d0 = blockIdx.y * 64;
    float pw = *pw_ptr;
#pragma unroll
    for (int i = 0; i < 8; i++) {
        int d = d0 + ty + i * 8;
        int jj = j0 + tx;
        float acc = 0.f;
        if (jj < 256) {
            float v = x[(((size_t)b * ND + d) * NK + p) * NS + jj];
            acc += (v >= 0.f) ? v : pw * v;
        }
        if (jj >= 1 && jj <= 256) {
            float v = x[(((size_t)b * ND + d) * NK + p + 128) * NS + jj - 1];
            acc += (v >= 0.f) ? v : pw * v;
        }
        t[ty + i * 8][tx] = acc;
    }
    __syncthreads();
#pragma unroll
    for (int i = 0; i < 4; i++) {
        int jl = ty + i * 8;
        int jj = j0 + jl;
        if (jj <= 256) {
            __half2 hv;
            hv.x = __float2half_rn(t[2 * tx][jl]);
            hv.y = __float2half_rn(t[2 * tx + 1][jl]);
            *(__half2*)&g_Af[(((size_t)b * NJ + jj) * 128 + p) * ND + d0 + 2 * tx] = hv;
        }
    }
}

// ---------------- fused main kernel: 512 threads, async prologue, pipelined GEMMs ----------------
__global__ __launch_bounds__(512, 1) void main_kernel(
    const float* __restrict__ b1g, const float* __restrict__ b2g, float* __restrict__ out)
{
    extern __shared__ char smc[];
    uint32_t sb = smem_u32(smc);
    float* s_b1 = (float*)(smc + SM_B1);
    float* s_b2 = (float*)(smc + SM_B2);
    int tid = threadIdx.x, w = tid >> 5, lane = tid & 31;
    int j = blockIdx.x, b = blockIdx.y;
    int pw = (w & 3) * 32, ow = (w >> 2) * 64;

    if (tid < 256) { s_b1[tid] = b1g[tid]; s_b2[tid] = b2g[tid]; }

    // ---- async prologue: group0 = W1 + A, group1 = W2 (lands during GEMM1) ----
    {
        const uint4* w14 = (const uint4*)g_W1f;
#pragma unroll
        for (int q = 0; q < 8; q++) {
            int idx = tid + q * 512;
            CP16(sb + SM_W1 + swz(idx >> 4, (idx & 15) << 4), (const void*)(w14 + idx));
        }
        const uint4* a4 = (const uint4*)(g_Af + ((size_t)b * NJ + j) * (128 * ND));
#pragma unroll
        for (int q = 0; q < 4; q++) {
            int idx = tid + q * 512;
            CP16(sb + SM_A + swz(idx >> 4, (idx & 15) << 4), (const void*)(a4 + idx));
        }
        CP_COMMIT();
        const uint4* w24 = (const uint4*)g_W2f;
#pragma unroll
        for (int q = 0; q < 8; q++) {
            int idx = tid + q * 512;
            CP16(sb + SM_W2 + swz(idx >> 4, (idx & 15) << 4), (const void*)(w24 + idx));
        }
        CP_COMMIT();
    }
    CP_WAIT(1);
    __syncthreads();

    // operand lane patterns
    int arow = lane & 15;
    uint32_t acb = (uint32_t)(lane >> 4) << 4;
    int brow = ((lane >> 3) & 1) * 8 + (lane & 7);
    uint32_t bcb = (uint32_t)((lane >> 4) & 1) << 4;
    uint32_t uW1 = sb + SM_W1, uW2 = sb + SM_W2, uA = sb + SM_A;
    int lr = lane >> 2, lc = (lane & 3) << 1;

    float acc[2][8][4];

    // ---- GEMM1: D1[p=128][o=256] = A[p][d] * W1[o][d] (pipelined) ----
#pragma unroll
    for (int mt = 0; mt < 2; mt++)
#pragma unroll
        for (int nt = 0; nt < 8; nt++)
#pragma unroll
            for (int q = 0; q < 4; q++) acc[mt][nt][q] = 0.f;
    gemm_pipe<false>(uA, uW1, pw + arow, ow + brow, acb, bcb, acc);

    // ---- epilogue1: Z = relu(D1 + nf*b1) -> fp16 at PERMUTED rows (no sync needed) ----
    float nf = (j == 0 || j == 256) ? 1.f : 2.f;
    int cW = ow >> 7;
    char* zB = smc + SM_Z + cW * 32768;
#pragma unroll
    for (int mt = 0; mt < 2; mt++) {
#pragma unroll
        for (int nt = 0; nt < 8; nt++) {
            int o = ow + nt * 8 + lc;
            int e = o & 127;
            float b0v = nf * s_b1[o], b1v = nf * s_b1[o + 1];
#pragma unroll
            for (int hf = 0; hf < 2; hf++) {
                int p = pw + mt * 16 + lr + hf * 8;
                int pl = p & 63;
                int nl = ((pl >> 4) << 4) + (((pl >> 1) & 1) << 3)
                       + (((pl >> 2) & 3) << 1) + (pl & 1);
                uint32_t row = (uint32_t)((p & 64) + nl);
                __half2 hv;
                hv.x = __float2half_rn(fmaxf(acc[mt][nt][hf * 2]     + b0v, 0.f));
                hv.y = __float2half_rn(fmaxf(acc[mt][nt][hf * 2 + 1] + b1v, 0.f));
                *(uint32_t*)(zB + swzZ(row, (uint32_t)e << 1)) = *(uint32_t*)&hv;
            }
        }
    }
    CP_WAIT(0);          // W2 landed
    __syncthreads();     // Z + W2 visible

    // ---- GEMM2 (transposed, pipelined): D2^T[o2=256][p=128] = W2[o2][e] * Z_c[p][e] ----
    int o2w = (w & 7) * 32, pw2 = (w >> 3) * 64;
    int ar2 = o2w + arow, br2 = pw2 + brow;
#pragma unroll 1
    for (int c = 0; c < 2; c++) {
        uint32_t uZ = sb + SM_Z + c * 32768;
#pragma unroll
        for (int mt = 0; mt < 2; mt++)
#pragma unroll
            for (int nt = 0; nt < 8; nt++)
#pragma unroll
                for (int q = 0; q < 4; q++) acc[mt][nt][q] = 0.f;
        gemm_pipe<true>(uW2, uZ, ar2, br2, acb, bcb, acc);

        // ---- out epilogue: 4x float4 contiguous per row (addressing computed here) ----
        int l0 = j * 128 - 64;
        int t4 = lane & 3;
        bool valid = (j > 0 || pw2 == 64) && (j < 256 || pw2 == 0);
        if (valid) {
            float* ob = out + (size_t)(b * 2 + c) * NO * TOUT;
#pragma unroll
            for (int mt = 0; mt < 2; mt++) {
#pragma unroll
                for (int hf = 0; hf < 2; hf++) {
                    int o2 = o2w + mt * 16 + lr + hf * 8;
                    float bo = s_b2[o2];
                    float* orow = ob + (size_t)o2 * TOUT + l0 + pw2 + t4 * 4;
#pragma unroll
                    for (int q = 0; q < 4; q++) {
                        float4 v;
                        v.x = acc[mt][2 * q][hf * 2]         + bo;
                        v.y = acc[mt][2 * q][hf * 2 + 1]     + bo;
                        v.z = acc[mt][2 * q + 1][hf * 2]     + bo;
                        v.w = acc[mt][2 * q + 1][hf * 2 + 1] + bo;
                        *(float4*)(orow + 16 * q) = v;
                    }
                }
            }
        }
    }
}

// ---------------------------------------------------------------------------
extern "C" void kernel_launch(void* const* d_in, const int* in_sizes, int n_in,
                              void* d_out, int out_size) {
    const float* x  = (const float*)d_in[0];
    const float* pw = (const float*)d_in[1];
    const float* w1 = (const float*)d_in[2];
    const float* b1 = (const float*)d_in[3];
    const float* w2 = (const float*)d_in[4];
    const float* b2 = (const float*)d_in[5];
    float* out = (float*)d_out;

    cudaFuncSetAttribute(main_kernel, cudaFuncAttributeMaxDynamicSharedMemorySize, SM_TOT);

    prep_all<<<dim3(9, 2, NB * 128 + 1), dim3(32, 8)>>>(x, pw, w1, w2);
    main_kernel<<<dim3(NJ, NB), 512, SM_TOT>>>(b1, b2, out);
}